// round 1
// baseline (speedup 1.0000x reference)
#include <cuda_runtime.h>
#include <math.h>

// ---------------- problem constants (fixed by the dataset) ----------------
#define NB   2
#define LQ   5440
#define CC   256
#define HH   4
#define LL   4
#define PP   8
#define HD   64          // CC / HH
#define LIN  5440        // 64*64 + 32*32 + 16*16 + 8*8
#define NQ   (NB * LQ)   // 10880
#define NKV  (NB * LIN)  // 10880
#define HLP  (HH * LL * PP)      // 128
#define HLP2 (HLP * 2)           // 256

// ---------------- scratch (device globals; no cudaMalloc allowed) ---------
__device__ float g_q[NQ * CC];          // src + query_pos
__device__ float g_value[NKV * CC];     // key_feat @ W_value + b
__device__ float g_offs[NQ * HLP2];     // q @ W_off + b
__device__ float g_attn[NQ * HLP];      // q @ W_attn + b  -> softmax in place
__device__ float g_sampled[NQ * CC];    // deformable-attention output (pre W_out)
__device__ float g_attnout[NQ * CC];    // sampled @ W_out + b

// ---------------- elementwise add: q = src + query_pos --------------------
__global__ void add_kernel(const float* __restrict__ a,
                           const float* __restrict__ b,
                           float* __restrict__ out, int n) {
    int i = blockIdx.x * blockDim.x + threadIdx.x;
    if (i < n) out[i] = a[i] + b[i];
}

// ---------------- SGEMM, K fixed at 256, with bias -------------------------
// C[M,N] = A[M,256] @ B[256,N] + bias[N]
// BM=64, BN=64, BK=16; 256 threads; 4x4 accum per thread.
#define BM 64
#define BN 64
#define BK 16
__global__ __launch_bounds__(256)
void gemm_k256_kernel(const float* __restrict__ A,
                      const float* __restrict__ B,
                      const float* __restrict__ bias,
                      float* __restrict__ C,
                      int M, int N) {
    __shared__ float As[BK][BM + 1];
    __shared__ float Bs[BK][BN];

    const int tid = threadIdx.x;
    const int tx  = tid & 15;      // 0..15 -> 4 output cols each
    const int ty  = tid >> 4;      // 0..15 -> 4 output rows each
    const int row0 = blockIdx.x * BM;
    const int col0 = blockIdx.y * BN;

    float acc[4][4] = {};

    for (int k0 = 0; k0 < 256; k0 += BK) {
        // load A tile (BM x BK = 1024 elems), store transposed As[k][m]
        #pragma unroll
        for (int i = 0; i < 4; i++) {
            int idx = tid + i * 256;
            int m = idx >> 4;          // /BK
            int k = idx & 15;
            As[k][m] = A[(size_t)(row0 + m) * 256 + k0 + k];
        }
        // load B tile (BK x BN = 1024 elems), Bs[k][n]
        #pragma unroll
        for (int i = 0; i < 4; i++) {
            int idx = tid + i * 256;
            int k = idx >> 6;          // /BN
            int n = idx & 63;
            Bs[k][n] = B[(size_t)(k0 + k) * N + col0 + n];
        }
        __syncthreads();

        #pragma unroll
        for (int k = 0; k < BK; k++) {
            float a[4], b[4];
            #pragma unroll
            for (int i = 0; i < 4; i++) a[i] = As[k][ty * 4 + i];
            #pragma unroll
            for (int j = 0; j < 4; j++) b[j] = Bs[k][tx * 4 + j];
            #pragma unroll
            for (int i = 0; i < 4; i++)
                #pragma unroll
                for (int j = 0; j < 4; j++)
                    acc[i][j] = fmaf(a[i], b[j], acc[i][j]);
        }
        __syncthreads();
    }

    #pragma unroll
    for (int i = 0; i < 4; i++) {
        int r = row0 + ty * 4 + i;
        #pragma unroll
        for (int j = 0; j < 4; j++) {
            int c = col0 + tx * 4 + j;
            C[(size_t)r * N + c] = acc[i][j] + bias[c];
        }
    }
}

// ---------------- softmax over L*P=32 per (n,q,h) --------------------------
// attn row layout: idx = h*32 + (l*8+p); one warp per head, 128 threads/block.
__global__ __launch_bounds__(128)
void softmax32_kernel(float* __restrict__ attn) {
    int nq  = blockIdx.x;
    int tid = threadIdx.x;
    float v = attn[(size_t)nq * HLP + tid];
    float m = v;
    #pragma unroll
    for (int o = 16; o > 0; o >>= 1) m = fmaxf(m, __shfl_xor_sync(0xffffffffu, m, o));
    float e = expf(v - m);
    float s = e;
    #pragma unroll
    for (int o = 16; o > 0; o >>= 1) s += __shfl_xor_sync(0xffffffffu, s, o);
    attn[(size_t)nq * HLP + tid] = e / s;
}

// ---------------- deformable bilinear sampling -----------------------------
// block = one query (nq); 256 threads = 4 heads x 64 dims.
__global__ __launch_bounds__(256)
void sample_kernel(const float* __restrict__ refpts,   // [N, Lq, L, 2]
                   float* __restrict__ out) {          // [NQ, 256] (h*64+d)
    const int lvlW[4]   = {64, 32, 16, 8};
    const int lvlS[4]   = {0, 4096, 5120, 5376};

    int nq  = blockIdx.x;
    int n   = nq / LQ;
    int tid = threadIdx.x;
    int h   = tid >> 6;
    int d   = tid & 63;

    const float* vbase = g_value + (size_t)n * LIN * CC + h * HD + d;
    float acc = 0.f;

    #pragma unroll
    for (int l = 0; l < 4; l++) {
        const int Wl = lvlW[l];
        const int Hl = lvlW[l];
        const float rx = refpts[(size_t)nq * (LL * 2) + l * 2 + 0];
        const float ry = refpts[(size_t)nq * (LL * 2) + l * 2 + 1];
        const float* vl = vbase + (size_t)lvlS[l] * CC;

        #pragma unroll
        for (int p = 0; p < 8; p++) {
            int pi = (h * LL + l) * PP + p;            // 0..127
            float ox = g_offs[(size_t)nq * HLP2 + pi * 2 + 0];
            float oy = g_offs[(size_t)nq * HLP2 + pi * 2 + 1];
            float a  = g_attn[(size_t)nq * HLP + pi];

            // pixel coords: loc*W - 0.5 = ref*W + off - 0.5
            float gx = rx * (float)Wl + ox - 0.5f;
            float gy = ry * (float)Hl + oy - 0.5f;
            float x0f = floorf(gx), y0f = floorf(gy);
            int x0 = (int)x0f, y0 = (int)y0f;
            float wx1 = gx - x0f, wy1 = gy - y0f;
            float wx0 = 1.f - wx1, wy0 = 1.f - wy1;

            bool xin0 = (x0 >= 0) & (x0 < Wl);
            bool xin1 = (x0 + 1 >= 0) & (x0 + 1 < Wl);
            bool yin0 = (y0 >= 0) & (y0 < Hl);
            bool yin1 = (y0 + 1 >= 0) & (y0 + 1 < Hl);
            int xc0 = min(max(x0, 0), Wl - 1);
            int xc1 = min(max(x0 + 1, 0), Wl - 1);
            int yc0 = min(max(y0, 0), Hl - 1);
            int yc1 = min(max(y0 + 1, 0), Hl - 1);

            float v00 = (yin0 && xin0) ? vl[(size_t)(yc0 * Wl + xc0) * CC] : 0.f;
            float v01 = (yin0 && xin1) ? vl[(size_t)(yc0 * Wl + xc1) * CC] : 0.f;
            float v10 = (yin1 && xin0) ? vl[(size_t)(yc1 * Wl + xc0) * CC] : 0.f;
            float v11 = (yin1 && xin1) ? vl[(size_t)(yc1 * Wl + xc1) * CC] : 0.f;

            acc += a * (v00 * wy0 * wx0 + v01 * wy0 * wx1 +
                        v10 * wy1 * wx0 + v11 * wy1 * wx1);
        }
    }
    out[(size_t)nq * CC + h * HD + d] = acc;
}

// ---------------- layernorm(src + attn_out) --------------------------------
__global__ __launch_bounds__(256)
void ln_kernel(const float* __restrict__ src,
               const float* __restrict__ attnout,
               const float* __restrict__ gamma,
               const float* __restrict__ beta,
               float* __restrict__ out) {
    int nq  = blockIdx.x;
    int tid = threadIdx.x;

    float x = src[(size_t)nq * CC + tid] + attnout[(size_t)nq * CC + tid];

    __shared__ float red[8];
    __shared__ float s_mean, s_rstd;

    // mean
    float s = x;
    #pragma unroll
    for (int o = 16; o > 0; o >>= 1) s += __shfl_xor_sync(0xffffffffu, s, o);
    if ((tid & 31) == 0) red[tid >> 5] = s;
    __syncthreads();
    if (tid == 0) {
        float t = 0.f;
        #pragma unroll
        for (int i = 0; i < 8; i++) t += red[i];
        s_mean = t * (1.f / 256.f);
    }
    __syncthreads();
    float mean = s_mean;

    // variance
    float dcen = x - mean;
    float v = dcen * dcen;
    #pragma unroll
    for (int o = 16; o > 0; o >>= 1) v += __shfl_xor_sync(0xffffffffu, v, o);
    if ((tid & 31) == 0) red[tid >> 5] = v;
    __syncthreads();
    if (tid == 0) {
        float t = 0.f;
        #pragma unroll
        for (int i = 0; i < 8; i++) t += red[i];
        s_rstd = rsqrtf(t * (1.f / 256.f) + 1e-5f);
    }
    __syncthreads();

    out[(size_t)nq * CC + tid] = dcen * s_rstd * gamma[tid] + beta[tid];
}

// ---------------- launcher --------------------------------------------------
extern "C" void kernel_launch(void* const* d_in, const int* in_sizes, int n_in,
                              void* d_out, int out_size) {
    const float* src_feat   = (const float*)d_in[0];
    const float* refpts     = (const float*)d_in[1];
    const float* key_feat   = (const float*)d_in[2];
    // d_in[3] spatial_shapes, d_in[4] level_start_index: compile-time constants
    const float* query_pos  = (const float*)d_in[5];
    const float* W_value    = (const float*)d_in[6];
    const float* b_value    = (const float*)d_in[7];
    const float* W_off      = (const float*)d_in[8];
    const float* b_off      = (const float*)d_in[9];
    const float* W_attn     = (const float*)d_in[10];
    const float* b_attn     = (const float*)d_in[11];
    const float* W_out      = (const float*)d_in[12];
    const float* b_out      = (const float*)d_in[13];
    const float* ln_g       = (const float*)d_in[14];
    const float* ln_b       = (const float*)d_in[15];
    float* out = (float*)d_out;

    float *q, *value, *offs, *attn, *sampled, *attnout;
    cudaGetSymbolAddress((void**)&q,       g_q);
    cudaGetSymbolAddress((void**)&value,   g_value);
    cudaGetSymbolAddress((void**)&offs,    g_offs);
    cudaGetSymbolAddress((void**)&attn,    g_attn);
    cudaGetSymbolAddress((void**)&sampled, g_sampled);
    cudaGetSymbolAddress((void**)&attnout, g_attnout);

    // 1. q = src + query_pos
    {
        int n = NQ * CC;
        add_kernel<<<(n + 255) / 256, 256>>>(src_feat, query_pos, q, n);
    }

    // 2. value = key_feat @ W_value + b_value     [10880 x 256]
    gemm_k256_kernel<<<dim3(NKV / BM, CC / BN), 256>>>(key_feat, W_value, b_value,
                                                       value, NKV, CC);
    // 3. offs = q @ W_off + b_off                 [10880 x 256]
    gemm_k256_kernel<<<dim3(NQ / BM, HLP2 / BN), 256>>>(q, W_off, b_off,
                                                        offs, NQ, HLP2);
    // 4. attn logits = q @ W_attn + b_attn        [10880 x 128]
    gemm_k256_kernel<<<dim3(NQ / BM, HLP / BN), 256>>>(q, W_attn, b_attn,
                                                       attn, NQ, HLP);
    // 5. softmax over 32 per head (in place)
    softmax32_kernel<<<NQ, 128>>>(attn);

    // 6. deformable sampling -> sampled [10880 x 256]
    sample_kernel<<<NQ, 256>>>(refpts, sampled);

    // 7. attn_out = sampled @ W_out + b_out
    gemm_k256_kernel<<<dim3(NQ / BM, CC / BN), 256>>>(sampled, W_out, b_out,
                                                      attnout, NQ, CC);
    // 8. layernorm(src + attn_out) -> out
    ln_kernel<<<NQ, 256>>>(src_feat, attnout, ln_g, ln_b, out);
}

// round 2
// speedup vs baseline: 1.1860x; 1.1860x over previous
#include <cuda_runtime.h>
#include <cuda_fp16.h>
#include <math.h>

// ---------------- problem constants (fixed by the dataset) ----------------
#define NB   2
#define LQ   5440
#define CC   256
#define HH   4
#define LL   4
#define PP   8
#define HD   64
#define LIN  5440
#define NQ   (NB * LQ)   // 10880
#define NKV  (NB * LIN)  // 10880
#define HLP  128
#define HLP2 256
#define NOA  384         // 256 (offs) + 128 (attn logits)

// ---------------- scratch (device globals; no cudaMalloc allowed) ---------
__device__ float  g_q[NQ * CC];            // src + query_pos
__device__ __half g_value_h[NKV * CC];     // value in fp16 for sampling
__device__ float  g_oa[NQ * NOA];          // [offs(256) | attn logits(128)]
__device__ float  g_Wpack[CC * NOA];       // [W_off | W_attn]
__device__ float  g_bpack[NOA];
__device__ float  g_sampled[NQ * CC];
__device__ float  g_attnout[NQ * CC];

// ---------------- elementwise add ------------------------------------------
__global__ void add_kernel(const float* __restrict__ a,
                           const float* __restrict__ b,
                           float* __restrict__ out, int n) {
    int i = blockIdx.x * blockDim.x + threadIdx.x;
    if (i < n) out[i] = a[i] + b[i];
}

// ---------------- pack [W_off | W_attn] ------------------------------------
__global__ void pack_w_kernel(const float* __restrict__ Woff,
                              const float* __restrict__ Wattn,
                              const float* __restrict__ boff,
                              const float* __restrict__ battn,
                              float* __restrict__ Wp,
                              float* __restrict__ bp) {
    int i = blockIdx.x * blockDim.x + threadIdx.x;
    if (i < CC * NOA) {
        int k = i / NOA, n = i % NOA;
        Wp[i] = (n < HLP2) ? Woff[k * HLP2 + n] : Wattn[k * HLP + (n - HLP2)];
    }
    if (i < NOA) bp[i] = (i < HLP2) ? boff[i] : battn[i - HLP2];
}

// ---------------- SGEMM: C[M,N] = A[M,256] @ B[256,N] + bias ---------------
// 128x64x16 tiles, 256 threads, 8x4 per thread, double-buffered smem.
#define GBM 128
#define GBN 64
#define GBK 16

template <typename OutT>
__global__ __launch_bounds__(256, 2)
void gemm_k256(const float* __restrict__ A,
               const float* __restrict__ B,
               const float* __restrict__ bias,
               OutT* __restrict__ C, int N) {
    __shared__ float As[2][GBK][GBM + 4];   // stride 132: float4 rows stay 16B aligned
    __shared__ float Bs[2][GBK][GBN];

    const int tid = threadIdx.x;
    const int tx  = tid & 15;       // 4 cols each
    const int ty  = tid >> 4;       // 8 rows each
    const int row0 = blockIdx.x * GBM;
    const int col0 = blockIdx.y * GBN;

    // A tile load: 128 rows x 4 float4; thread handles (am0, ak0) and (am0+64, ak0)
    const int am0 = tid >> 2;               // 0..63
    const int ak0 = (tid & 3) << 2;         // 0,4,8,12
    // B tile load: 16 rows x 16 float4
    const int bk = tid >> 4;                // 0..15
    const int bn = (tid & 15) << 2;         // 0..60

    const float* Aptr = A + (size_t)row0 * 256;
    const float* Bptr = B + col0;

    float4 a0 = *(const float4*)(Aptr + (size_t)am0 * 256 + ak0);
    float4 a1 = *(const float4*)(Aptr + (size_t)(am0 + 64) * 256 + ak0);
    float4 b0 = *(const float4*)(Bptr + (size_t)bk * N + bn);

    float acc[8][4] = {};

    int buf = 0;
    #pragma unroll 1
    for (int t = 0; t < 16; t++) {
        // commit prefetched tile to smem[buf]
        As[buf][ak0 + 0][am0] = a0.x;
        As[buf][ak0 + 1][am0] = a0.y;
        As[buf][ak0 + 2][am0] = a0.z;
        As[buf][ak0 + 3][am0] = a0.w;
        As[buf][ak0 + 0][am0 + 64] = a1.x;
        As[buf][ak0 + 1][am0 + 64] = a1.y;
        As[buf][ak0 + 2][am0 + 64] = a1.z;
        As[buf][ak0 + 3][am0 + 64] = a1.w;
        *(float4*)&Bs[buf][bk][bn] = b0;
        __syncthreads();

        if (t < 15) {
            int k0 = (t + 1) * GBK;
            a0 = *(const float4*)(Aptr + (size_t)am0 * 256 + k0 + ak0);
            a1 = *(const float4*)(Aptr + (size_t)(am0 + 64) * 256 + k0 + ak0);
            b0 = *(const float4*)(Bptr + (size_t)(k0 + bk) * N + bn);
        }

        #pragma unroll
        for (int k = 0; k < GBK; k++) {
            float4 av0 = *(const float4*)&As[buf][k][ty * 8];
            float4 av1 = *(const float4*)&As[buf][k][ty * 8 + 4];
            float4 bv  = *(const float4*)&Bs[buf][k][tx * 4];
            float a[8] = {av0.x, av0.y, av0.z, av0.w, av1.x, av1.y, av1.z, av1.w};
            float b[4] = {bv.x, bv.y, bv.z, bv.w};
            #pragma unroll
            for (int i = 0; i < 8; i++)
                #pragma unroll
                for (int j = 0; j < 4; j++)
                    acc[i][j] = fmaf(a[i], b[j], acc[i][j]);
        }
        buf ^= 1;
    }

    float bias4[4];
    #pragma unroll
    for (int j = 0; j < 4; j++) bias4[j] = bias[col0 + tx * 4 + j];

    #pragma unroll
    for (int i = 0; i < 8; i++) {
        int r = row0 + ty * 8 + i;
        int c = col0 + tx * 4;
        #pragma unroll
        for (int j = 0; j < 4; j++) {
            float v = acc[i][j] + bias4[j];
            C[(size_t)r * N + c + j] = (OutT)v;
        }
    }
}

// ---------------- fused softmax + deformable sampling ----------------------
// one block per query: 256 threads = 4 heads x 64 dims; value in fp16.
__global__ __launch_bounds__(256)
void sample_kernel(const float* __restrict__ refpts,     // [N,Lq,L,2]
                   const float* __restrict__ oa,         // [NQ,384]
                   const __half* __restrict__ value,     // [NKV,256]
                   float* __restrict__ out) {            // [NQ,256]
    __shared__ float s_off[HLP2];
    __shared__ float s_attn[HLP];
    __shared__ float s_ref[8];

    const int nq  = blockIdx.x;
    const int tid = threadIdx.x;
    const float* row = oa + (size_t)nq * NOA;

    s_off[tid] = row[tid];
    if (tid < HLP) {
        float v = row[HLP2 + tid];
        float m = v;
        #pragma unroll
        for (int o = 16; o > 0; o >>= 1) m = fmaxf(m, __shfl_xor_sync(0xffffffffu, m, o));
        float e = expf(v - m);
        float s = e;
        #pragma unroll
        for (int o = 16; o > 0; o >>= 1) s += __shfl_xor_sync(0xffffffffu, s, o);
        s_attn[tid] = e / s;
    }
    if (tid < 8) s_ref[tid] = refpts[(size_t)nq * 8 + tid];
    __syncthreads();

    const int h = tid >> 6;
    const int d = tid & 63;
    const int lvlS[4] = {0, 4096, 5120, 5376};

    const __half* vbase = value + (size_t)(nq / LQ) * LIN * CC + h * HD + d;
    float acc = 0.f;

    #pragma unroll
    for (int l = 0; l < 4; l++) {
        const int Wl = 64 >> l;
        const float gxb = s_ref[l * 2 + 0] * (float)Wl - 0.5f;
        const float gyb = s_ref[l * 2 + 1] * (float)Wl - 0.5f;
        const __half* vl = vbase + (size_t)lvlS[l] * CC;

        #pragma unroll
        for (int p = 0; p < 8; p++) {
            int pi = (h * LL + l) * PP + p;
            float gx = gxb + s_off[pi * 2 + 0];
            float gy = gyb + s_off[pi * 2 + 1];
            float a  = s_attn[pi];

            float x0f = floorf(gx), y0f = floorf(gy);
            int x0 = (int)x0f, y0 = (int)y0f;
            float wx1 = gx - x0f, wy1 = gy - y0f;
            float wx0 = 1.f - wx1, wy0 = 1.f - wy1;

            bool xin0 = (x0 >= 0) & (x0 < Wl);
            bool xin1 = (x0 + 1 >= 0) & (x0 + 1 < Wl);
            bool yin0 = (y0 >= 0) & (y0 < Wl);
            bool yin1 = (y0 + 1 >= 0) & (y0 + 1 < Wl);
            int xc0 = min(max(x0, 0), Wl - 1);
            int xc1 = min(max(x0 + 1, 0), Wl - 1);
            int yc0 = min(max(y0, 0), Wl - 1);
            int yc1 = min(max(y0 + 1, 0), Wl - 1);

            float v00 = (yin0 && xin0) ? __half2float(vl[(size_t)(yc0 * Wl + xc0) * CC]) : 0.f;
            float v01 = (yin0 && xin1) ? __half2float(vl[(size_t)(yc0 * Wl + xc1) * CC]) : 0.f;
            float v10 = (yin1 && xin0) ? __half2float(vl[(size_t)(yc1 * Wl + xc0) * CC]) : 0.f;
            float v11 = (yin1 && xin1) ? __half2float(vl[(size_t)(yc1 * Wl + xc1) * CC]) : 0.f;

            acc += a * (v00 * wy0 * wx0 + v01 * wy0 * wx1 +
                        v10 * wy1 * wx0 + v11 * wy1 * wx1);
        }
    }
    out[(size_t)nq * CC + tid] = acc;
}

// ---------------- layernorm(src + attn_out) --------------------------------
__global__ __launch_bounds__(256)
void ln_kernel(const float* __restrict__ src,
               const float* __restrict__ attnout,
               const float* __restrict__ gamma,
               const float* __restrict__ beta,
               float* __restrict__ out) {
    int nq  = blockIdx.x;
    int tid = threadIdx.x;

    float x = src[(size_t)nq * CC + tid] + attnout[(size_t)nq * CC + tid];

    __shared__ float red[8];
    __shared__ float s_mean, s_rstd;

    float s = x;
    #pragma unroll
    for (int o = 16; o > 0; o >>= 1) s += __shfl_xor_sync(0xffffffffu, s, o);
    if ((tid & 31) == 0) red[tid >> 5] = s;
    __syncthreads();
    if (tid == 0) {
        float t = 0.f;
        #pragma unroll
        for (int i = 0; i < 8; i++) t += red[i];
        s_mean = t * (1.f / 256.f);
    }
    __syncthreads();
    float mean = s_mean;

    float dcen = x - mean;
    float v = dcen * dcen;
    #pragma unroll
    for (int o = 16; o > 0; o >>= 1) v += __shfl_xor_sync(0xffffffffu, v, o);
    if ((tid & 31) == 0) red[tid >> 5] = v;
    __syncthreads();
    if (tid == 0) {
        float t = 0.f;
        #pragma unroll
        for (int i = 0; i < 8; i++) t += red[i];
        s_rstd = rsqrtf(t * (1.f / 256.f) + 1e-5f);
    }
    __syncthreads();

    out[(size_t)nq * CC + tid] = dcen * s_rstd * gamma[tid] + beta[tid];
}

// ---------------- launcher --------------------------------------------------
extern "C" void kernel_launch(void* const* d_in, const int* in_sizes, int n_in,
                              void* d_out, int out_size) {
    const float* src_feat   = (const float*)d_in[0];
    const float* refpts     = (const float*)d_in[1];
    const float* key_feat   = (const float*)d_in[2];
    const float* query_pos  = (const float*)d_in[5];
    const float* W_value    = (const float*)d_in[6];
    const float* b_value    = (const float*)d_in[7];
    const float* W_off      = (const float*)d_in[8];
    const float* b_off      = (const float*)d_in[9];
    const float* W_attn     = (const float*)d_in[10];
    const float* b_attn     = (const float*)d_in[11];
    const float* W_out      = (const float*)d_in[12];
    const float* b_out      = (const float*)d_in[13];
    const float* ln_g       = (const float*)d_in[14];
    const float* ln_b       = (const float*)d_in[15];
    float* out = (float*)d_out;

    float *q, *oa, *Wp, *bp, *sampled, *attnout;
    __half* value_h;
    cudaGetSymbolAddress((void**)&q,       g_q);
    cudaGetSymbolAddress((void**)&value_h, g_value_h);
    cudaGetSymbolAddress((void**)&oa,      g_oa);
    cudaGetSymbolAddress((void**)&Wp,      g_Wpack);
    cudaGetSymbolAddress((void**)&bp,      g_bpack);
    cudaGetSymbolAddress((void**)&sampled, g_sampled);
    cudaGetSymbolAddress((void**)&attnout, g_attnout);

    // 1. q = src + query_pos ;  pack [W_off|W_attn]
    add_kernel<<<(NQ * CC + 255) / 256, 256>>>(src_feat, query_pos, q, NQ * CC);
    pack_w_kernel<<<(CC * NOA + 255) / 256, 256>>>(W_off, W_attn, b_off, b_attn, Wp, bp);

    // 2. value (fp16 out)     [10880 x 256]
    gemm_k256<__half><<<dim3(NKV / GBM, CC / GBN), 256>>>(key_feat, W_value, b_value,
                                                          value_h, CC);
    // 3. offs|attn logits     [10880 x 384]
    gemm_k256<float><<<dim3(NQ / GBM, NOA / GBN), 256>>>(q, Wp, bp, oa, NOA);

    // 4. fused softmax + deformable sampling
    sample_kernel<<<NQ, 256>>>(refpts, oa, value_h, sampled);

    // 5. out projection
    gemm_k256<float><<<dim3(NQ / GBM, CC / GBN), 256>>>(sampled, W_out, b_out,
                                                        attnout, CC);
    // 6. layernorm
    ln_kernel<<<NQ, 256>>>(src_feat, attnout, ln_g, ln_b, out);
}

// round 3
// speedup vs baseline: 2.1477x; 1.8108x over previous
#include <cuda_runtime.h>
#include <cuda_fp16.h>
#include <math.h>

// ---------------- problem constants ----------------------------------------
#define NB   2
#define LQ   5440
#define CC   256
#define HH   4
#define LL   4
#define PP   8
#define HD   64
#define LIN  5440
#define NQ   (NB * LQ)   // 10880
#define NKV  (NB * LIN)  // 10880
#define HLP  128
#define HLP2 256
#define NOA  384         // 256 offs + 128 attn logits

// ---------------- scratch ---------------------------------------------------
__device__ __half g_q_h[NQ * CC];
__device__ __half g_key_h[NKV * CC];
__device__ __half g_value_h[NKV * CC];
__device__ float  g_oa[NQ * NOA];
__device__ __half g_Wv_h[CC * CC];
__device__ __half g_Woa_h[CC * NOA];
__device__ __half g_Wo_h[CC * CC];
__device__ float  g_boa[NOA];
__device__ __half g_sampled_h[NQ * CC];
__device__ float  g_attnout[NQ * CC];

// ---------------- prep: q=src+pos (fp16), key->fp16 -------------------------
__global__ void prep_inputs_kernel(const float* __restrict__ src,
                                   const float* __restrict__ pos,
                                   const float* __restrict__ key,
                                   __half* __restrict__ qh,
                                   __half* __restrict__ keyh) {
    int i = blockIdx.x * blockDim.x + threadIdx.x;
    if (i < NQ * CC)  qh[i]   = __float2half(src[i] + pos[i]);
    if (i < NKV * CC) keyh[i] = __float2half(key[i]);
}

// ---------------- prep: weights -> fp16 (W_off|W_attn packed) ---------------
__global__ void prep_weights_kernel(const float* __restrict__ Wv,
                                    const float* __restrict__ Woff,
                                    const float* __restrict__ Wattn,
                                    const float* __restrict__ boff,
                                    const float* __restrict__ battn,
                                    const float* __restrict__ Wo,
                                    __half* __restrict__ Wvh,
                                    __half* __restrict__ Woah,
                                    __half* __restrict__ Woh,
                                    float* __restrict__ boa) {
    int i = blockIdx.x * blockDim.x + threadIdx.x;
    if (i < CC * CC) {
        Wvh[i] = __float2half(Wv[i]);
        Woh[i] = __float2half(Wo[i]);
    }
    if (i < CC * NOA) {
        int k = i / NOA, n = i % NOA;
        float w = (n < HLP2) ? Woff[k * HLP2 + n] : Wattn[k * HLP + (n - HLP2)];
        Woah[i] = __float2half(w);
    }
    if (i < NOA) boa[i] = (i < HLP2) ? boff[i] : battn[i - HLP2];
}

// ---------------- HGEMM (fp16 in, fp32 accum): C=A[M,256]@B[256,N]+bias -----
#define GBM 128
#define GBN 64
#define GBK 32
#define AS_STRIDE 40   // 32 + 8 halfs pad
#define BS_STRIDE 72   // 64 + 8 halfs pad

__device__ __forceinline__ void ldm_x4(unsigned& r0, unsigned& r1,
                                       unsigned& r2, unsigned& r3,
                                       unsigned addr) {
    asm volatile("ldmatrix.sync.aligned.m8n8.x4.shared.b16 {%0,%1,%2,%3}, [%4];"
                 : "=r"(r0), "=r"(r1), "=r"(r2), "=r"(r3) : "r"(addr));
}
__device__ __forceinline__ void ldm_x4_t(unsigned& r0, unsigned& r1,
                                         unsigned& r2, unsigned& r3,
                                         unsigned addr) {
    asm volatile("ldmatrix.sync.aligned.m8n8.x4.trans.shared.b16 {%0,%1,%2,%3}, [%4];"
                 : "=r"(r0), "=r"(r1), "=r"(r2), "=r"(r3) : "r"(addr));
}
__device__ __forceinline__ void mma16816(float& c0, float& c1, float& c2, float& c3,
                                         unsigned a0, unsigned a1, unsigned a2, unsigned a3,
                                         unsigned b0, unsigned b1) {
    asm volatile(
        "mma.sync.aligned.m16n8k16.row.col.f32.f16.f16.f32 "
        "{%0,%1,%2,%3}, {%4,%5,%6,%7}, {%8,%9}, {%0,%1,%2,%3};"
        : "+f"(c0), "+f"(c1), "+f"(c2), "+f"(c3)
        : "r"(a0), "r"(a1), "r"(a2), "r"(a3), "r"(b0), "r"(b1));
}

template <typename OutT>
__global__ __launch_bounds__(256, 2)
void hgemm_k256(const __half* __restrict__ A,
                const __half* __restrict__ B,
                const float* __restrict__ bias,
                OutT* __restrict__ C, int N) {
    __shared__ __half As[2][GBM][AS_STRIDE];
    __shared__ __half Bs[2][GBK][BS_STRIDE];

    const int tid  = threadIdx.x;
    const int lane = tid & 31;
    const int warp = tid >> 5;
    const int wm = warp >> 1;          // 0..3  -> m offset 32*wm
    const int wn = warp & 1;           // 0..1  -> n offset 32*wn
    const int row0 = blockIdx.x * GBM;
    const int col0 = blockIdx.y * GBN;

    // global load mapping
    const int ar = tid >> 2;           // 0..63 (and +64)
    const int ac = (tid & 3) << 3;     // 0,8,16,24
    const int br = tid >> 3;           // 0..31
    const int bc = (tid & 7) << 3;     // 0..56

    const __half* Aptr = A + (size_t)row0 * 256;
    const __half* Bptr = B + col0;

    uint4 pa0 = *(const uint4*)(Aptr + (size_t)ar * 256 + ac);
    uint4 pa1 = *(const uint4*)(Aptr + (size_t)(ar + 64) * 256 + ac);
    uint4 pb  = *(const uint4*)(Bptr + (size_t)br * N + bc);

    float acc[2][4][4] = {};

    // ldmatrix source addresses (per buffer)
    // A: row = lane&15 within m16 tile, col block = (lane>>4)*8
    const int a_lrow = lane & 15;
    const int a_lcol = (lane >> 4) << 3;
    // B(trans): row(k) = lane&15, col = (lane>>4)*8
    const int b_lrow = lane & 15;
    const int b_lcol = (lane >> 4) << 3;

    int buf = 0;
    #pragma unroll 1
    for (int t = 0; t < 8; t++) {
        *(uint4*)&As[buf][ar][ac]      = pa0;
        *(uint4*)&As[buf][ar + 64][ac] = pa1;
        *(uint4*)&Bs[buf][br][bc]      = pb;
        __syncthreads();

        if (t < 7) {
            int k0 = (t + 1) * GBK;
            pa0 = *(const uint4*)(Aptr + (size_t)ar * 256 + k0 + ac);
            pa1 = *(const uint4*)(Aptr + (size_t)(ar + 64) * 256 + k0 + ac);
            pb  = *(const uint4*)(Bptr + (size_t)(k0 + br) * N + bc);
        }

        #pragma unroll
        for (int ks = 0; ks < 2; ks++) {
            const int kk = ks * 16;
            unsigned af[2][4], bf[4][2];
            #pragma unroll
            for (int mt = 0; mt < 2; mt++) {
                unsigned addr = (unsigned)__cvta_generic_to_shared(
                    &As[buf][wm * 32 + mt * 16 + a_lrow][kk + a_lcol]);
                ldm_x4(af[mt][0], af[mt][1], af[mt][2], af[mt][3], addr);
            }
            #pragma unroll
            for (int nt = 0; nt < 2; nt++) {
                unsigned addr = (unsigned)__cvta_generic_to_shared(
                    &Bs[buf][kk + b_lrow][wn * 32 + nt * 16 + b_lcol]);
                unsigned r0, r1, r2, r3;
                ldm_x4_t(r0, r1, r2, r3, addr);
                bf[nt * 2 + 0][0] = r0; bf[nt * 2 + 0][1] = r1;
                bf[nt * 2 + 1][0] = r2; bf[nt * 2 + 1][1] = r3;
            }
            #pragma unroll
            for (int mt = 0; mt < 2; mt++)
                #pragma unroll
                for (int j = 0; j < 4; j++)
                    mma16816(acc[mt][j][0], acc[mt][j][1], acc[mt][j][2], acc[mt][j][3],
                             af[mt][0], af[mt][1], af[mt][2], af[mt][3],
                             bf[j][0], bf[j][1]);
        }
        __syncthreads();
        buf ^= 1;
    }

    // epilogue: c0,c1 -> row g cols 2t,2t+1 ; c2,c3 -> row g+8
    const int g  = lane >> 2;
    const int tq = (lane & 3) << 1;
    #pragma unroll
    for (int mt = 0; mt < 2; mt++) {
        int r_lo = row0 + wm * 32 + mt * 16 + g;
        #pragma unroll
        for (int j = 0; j < 4; j++) {
            int c = col0 + wn * 32 + j * 8 + tq;
            float b0 = bias[c], b1 = bias[c + 1];
            C[(size_t)r_lo * N + c]           = (OutT)(acc[mt][j][0] + b0);
            C[(size_t)r_lo * N + c + 1]       = (OutT)(acc[mt][j][1] + b1);
            C[(size_t)(r_lo + 8) * N + c]     = (OutT)(acc[mt][j][2] + b0);
            C[(size_t)(r_lo + 8) * N + c + 1] = (OutT)(acc[mt][j][3] + b1);
        }
    }
}

// ---------------- fused softmax + deformable sampling (half2) ---------------
// one block per query: 128 threads = 4 heads x 32 lanes, each lane 2 dims.
__global__ __launch_bounds__(128)
void sample_kernel(const float* __restrict__ refpts,
                   const float* __restrict__ oa,
                   const __half* __restrict__ value,
                   __half* __restrict__ out) {
    __shared__ float s_off[HLP2];
    __shared__ float s_attn[HLP];
    __shared__ float s_ref[8];

    const int nq  = blockIdx.x;
    const int tid = threadIdx.x;
    const float* row = oa + (size_t)nq * NOA;

    s_off[tid]       = row[tid];
    s_off[tid + 128] = row[tid + 128];
    {
        float v = row[HLP2 + tid];
        float m = v;
        #pragma unroll
        for (int o = 16; o > 0; o >>= 1) m = fmaxf(m, __shfl_xor_sync(0xffffffffu, m, o));
        float e = expf(v - m);
        float s = e;
        #pragma unroll
        for (int o = 16; o > 0; o >>= 1) s += __shfl_xor_sync(0xffffffffu, s, o);
        s_attn[tid] = e / s;
    }
    if (tid < 8) s_ref[tid] = refpts[(size_t)nq * 8 + tid];
    __syncthreads();

    const int h    = tid >> 5;
    const int lane = tid & 31;
    const int lvlS[4] = {0, 4096, 5120, 5376};

    // half2 view: row stride CC/2 = 128 half2
    const __half2* vbase = (const __half2*)(value + (size_t)(nq / LQ) * LIN * CC)
                           + h * (HD / 2) + lane;
    float2 acc = {0.f, 0.f};

    #pragma unroll
    for (int l = 0; l < 4; l++) {
        const int Wl = 64 >> l;
        const float gxb = s_ref[l * 2 + 0] * (float)Wl - 0.5f;
        const float gyb = s_ref[l * 2 + 1] * (float)Wl - 0.5f;
        const __half2* vl = vbase + (size_t)lvlS[l] * (CC / 2);

        #pragma unroll
        for (int p = 0; p < 8; p++) {
            int pi = (h * LL + l) * PP + p;
            float gx = gxb + s_off[pi * 2 + 0];
            float gy = gyb + s_off[pi * 2 + 1];
            float a  = s_attn[pi];

            float x0f = floorf(gx), y0f = floorf(gy);
            int x0 = (int)x0f, y0 = (int)y0f;
            float wx1 = gx - x0f, wy1 = gy - y0f;
            float wx0 = 1.f - wx1, wy0 = 1.f - wy1;

            bool xin0 = (x0 >= 0) & (x0 < Wl);
            bool xin1 = (x0 + 1 >= 0) & (x0 + 1 < Wl);
            bool yin0 = (y0 >= 0) & (y0 < Wl);
            bool yin1 = (y0 + 1 >= 0) & (y0 + 1 < Wl);
            int xc0 = min(max(x0, 0), Wl - 1);
            int xc1 = min(max(x0 + 1, 0), Wl - 1);
            int yc0 = min(max(y0, 0), Wl - 1);
            int yc1 = min(max(y0 + 1, 0), Wl - 1);

            float2 z = {0.f, 0.f};
            float2 v00 = (yin0 && xin0) ? __half22float2(vl[(size_t)(yc0 * Wl + xc0) * 128]) : z;
            float2 v01 = (yin0 && xin1) ? __half22float2(vl[(size_t)(yc0 * Wl + xc1) * 128]) : z;
            float2 v10 = (yin1 && xin0) ? __half22float2(vl[(size_t)(yc1 * Wl + xc0) * 128]) : z;
            float2 v11 = (yin1 && xin1) ? __half22float2(vl[(size_t)(yc1 * Wl + xc1) * 128]) : z;

            float w00 = wy0 * wx0, w01 = wy0 * wx1, w10 = wy1 * wx0, w11 = wy1 * wx1;
            acc.x += a * (v00.x * w00 + v01.x * w01 + v10.x * w10 + v11.x * w11);
            acc.y += a * (v00.y * w00 + v01.y * w01 + v10.y * w10 + v11.y * w11);
        }
    }
    ((__half2*)(out + (size_t)nq * CC))[h * (HD / 2) + lane] = __float22half2_rn(acc);
}

// ---------------- layernorm(src + attn_out) --------------------------------
__global__ __launch_bounds__(256)
void ln_kernel(const float* __restrict__ src,
               const float* __restrict__ attnout,
               const float* __restrict__ gamma,
               const float* __restrict__ beta,
               float* __restrict__ out) {
    int nq  = blockIdx.x;
    int tid = threadIdx.x;

    float x = src[(size_t)nq * CC + tid] + attnout[(size_t)nq * CC + tid];

    __shared__ float red[8];
    __shared__ float s_mean, s_rstd;

    float s = x;
    #pragma unroll
    for (int o = 16; o > 0; o >>= 1) s += __shfl_xor_sync(0xffffffffu, s, o);
    if ((tid & 31) == 0) red[tid >> 5] = s;
    __syncthreads();
    if (tid == 0) {
        float t = 0.f;
        #pragma unroll
        for (int i = 0; i < 8; i++) t += red[i];
        s_mean = t * (1.f / 256.f);
    }
    __syncthreads();
    float mean = s_mean;

    float dcen = x - mean;
    float v = dcen * dcen;
    #pragma unroll
    for (int o = 16; o > 0; o >>= 1) v += __shfl_xor_sync(0xffffffffu, v, o);
    if ((tid & 31) == 0) red[tid >> 5] = v;
    __syncthreads();
    if (tid == 0) {
        float t = 0.f;
        #pragma unroll
        for (int i = 0; i < 8; i++) t += red[i];
        s_rstd = rsqrtf(t * (1.f / 256.f) + 1e-5f);
    }
    __syncthreads();

    out[(size_t)nq * CC + tid] = dcen * s_rstd * gamma[tid] + beta[tid];
}

// ---------------- launcher --------------------------------------------------
extern "C" void kernel_launch(void* const* d_in, const int* in_sizes, int n_in,
                              void* d_out, int out_size) {
    const float* src_feat   = (const float*)d_in[0];
    const float* refpts     = (const float*)d_in[1];
    const float* key_feat   = (const float*)d_in[2];
    const float* query_pos  = (const float*)d_in[5];
    const float* W_value    = (const float*)d_in[6];
    const float* b_value    = (const float*)d_in[7];
    const float* W_off      = (const float*)d_in[8];
    const float* b_off      = (const float*)d_in[9];
    const float* W_attn     = (const float*)d_in[10];
    const float* b_attn     = (const float*)d_in[11];
    const float* W_out      = (const float*)d_in[12];
    const float* b_out      = (const float*)d_in[13];
    const float* ln_g       = (const float*)d_in[14];
    const float* ln_b       = (const float*)d_in[15];
    float* out = (float*)d_out;

    __half *qh, *keyh, *valueh, *Wvh, *Woah, *Woh, *sampledh;
    float *oa, *boa, *attnout;
    cudaGetSymbolAddress((void**)&qh,       g_q_h);
    cudaGetSymbolAddress((void**)&keyh,     g_key_h);
    cudaGetSymbolAddress((void**)&valueh,   g_value_h);
    cudaGetSymbolAddress((void**)&oa,       g_oa);
    cudaGetSymbolAddress((void**)&Wvh,      g_Wv_h);
    cudaGetSymbolAddress((void**)&Woah,     g_Woa_h);
    cudaGetSymbolAddress((void**)&Woh,      g_Wo_h);
    cudaGetSymbolAddress((void**)&boa,      g_boa);
    cudaGetSymbolAddress((void**)&sampledh, g_sampled_h);
    cudaGetSymbolAddress((void**)&attnout,  g_attnout);

    // 1. prep inputs + weights (fp16)
    prep_inputs_kernel<<<(NQ * CC + 255) / 256, 256>>>(src_feat, query_pos, key_feat,
                                                       qh, keyh);
    prep_weights_kernel<<<(CC * NOA + 255) / 256, 256>>>(W_value, W_off, W_attn,
                                                         b_off, b_attn, W_out,
                                                         Wvh, Woah, Woh, boa);

    // 2. value = key @ Wv + b (fp16 out)      [10880 x 256]
    hgemm_k256<__half><<<dim3(NKV / GBM, CC / GBN), 256>>>(keyh, Wvh, b_value,
                                                           valueh, CC);
    // 3. offs|attn = q @ Woa + boa            [10880 x 384]
    hgemm_k256<float><<<dim3(NQ / GBM, NOA / GBN), 256>>>(qh, Woah, boa, oa, NOA);

    // 4. fused softmax + sampling -> sampled (fp16)
    sample_kernel<<<NQ, 128>>>(refpts, oa, valueh, sampledh);

    // 5. attn_out = sampled @ Wo + b
    hgemm_k256<float><<<dim3(NQ / GBM, CC / GBN), 256>>>(sampledh, Woh, b_out,
                                                         attnout, CC);
    // 6. layernorm
    ln_kernel<<<NQ, 256>>>(src_feat, attnout, ln_g, ln_b, out);
}

// round 4
// speedup vs baseline: 3.3392x; 1.5548x over previous
#include <cuda_runtime.h>
#include <cuda_fp16.h>
#include <math.h>

// ---------------- problem constants ----------------------------------------
#define NB   2
#define LQ   5440
#define CC   256
#define HH   4
#define LL   4
#define PP   8
#define HD   64
#define LIN  5440
#define NQ   (NB * LQ)   // 10880
#define NKV  (NB * LIN)  // 10880
#define HLP  128
#define HLP2 256
#define NOA  384

// ---------------- scratch ---------------------------------------------------
__device__ __half g_q_h[NQ * CC];
__device__ __half g_key_h[NKV * CC];
__device__ __half g_value_h[NKV * CC];
__device__ float  g_oa[NQ * NOA];
__device__ __half g_Wv_h[CC * CC];
__device__ __half g_Woa_h[CC * NOA];
__device__ __half g_Wo_h[CC * CC];
__device__ float  g_boa[NOA];
__device__ __half g_sampled_h[NQ * CC];
__device__ float  g_attnout[NQ * CC];

// ---------------- prep: q=src+pos (fp16), key->fp16, vectorized x8 ----------
#define N8 (NQ * CC / 8)
__global__ __launch_bounds__(256)
void prep_inputs_kernel(const float* __restrict__ src,
                        const float* __restrict__ pos,
                        const float* __restrict__ key,
                        __half* __restrict__ qh,
                        __half* __restrict__ keyh) {
    int i = blockIdx.x * blockDim.x + threadIdx.x;
    if (i < N8) {
        float4 s0 = ((const float4*)src)[i * 2];
        float4 s1 = ((const float4*)src)[i * 2 + 1];
        float4 p0 = ((const float4*)pos)[i * 2];
        float4 p1 = ((const float4*)pos)[i * 2 + 1];
        __half2 h0 = __floats2half2_rn(s0.x + p0.x, s0.y + p0.y);
        __half2 h1 = __floats2half2_rn(s0.z + p0.z, s0.w + p0.w);
        __half2 h2 = __floats2half2_rn(s1.x + p1.x, s1.y + p1.y);
        __half2 h3 = __floats2half2_rn(s1.z + p1.z, s1.w + p1.w);
        uint4 o;
        o.x = *(unsigned*)&h0; o.y = *(unsigned*)&h1;
        o.z = *(unsigned*)&h2; o.w = *(unsigned*)&h3;
        ((uint4*)qh)[i] = o;
    } else if (i < 2 * N8) {
        int j = i - N8;
        float4 k0 = ((const float4*)key)[j * 2];
        float4 k1 = ((const float4*)key)[j * 2 + 1];
        __half2 h0 = __floats2half2_rn(k0.x, k0.y);
        __half2 h1 = __floats2half2_rn(k0.z, k0.w);
        __half2 h2 = __floats2half2_rn(k1.x, k1.y);
        __half2 h3 = __floats2half2_rn(k1.z, k1.w);
        uint4 o;
        o.x = *(unsigned*)&h0; o.y = *(unsigned*)&h1;
        o.z = *(unsigned*)&h2; o.w = *(unsigned*)&h3;
        ((uint4*)keyh)[j] = o;
    }
}

// ---------------- prep: weights -> fp16 -------------------------------------
__global__ void prep_weights_kernel(const float* __restrict__ Wv,
                                    const float* __restrict__ Woff,
                                    const float* __restrict__ Wattn,
                                    const float* __restrict__ boff,
                                    const float* __restrict__ battn,
                                    const float* __restrict__ Wo,
                                    __half* __restrict__ Wvh,
                                    __half* __restrict__ Woah,
                                    __half* __restrict__ Woh,
                                    float* __restrict__ boa) {
    int i = blockIdx.x * blockDim.x + threadIdx.x;
    if (i < CC * CC) {
        Wvh[i] = __float2half(Wv[i]);
        Woh[i] = __float2half(Wo[i]);
    }
    if (i < CC * NOA) {
        int k = i / NOA, n = i % NOA;
        float w = (n < HLP2) ? Woff[k * HLP2 + n] : Wattn[k * HLP + (n - HLP2)];
        Woah[i] = __float2half(w);
    }
    if (i < NOA) boa[i] = (i < HLP2) ? boff[i] : battn[i - HLP2];
}

// ---------------- HGEMM: cp.async 3-stage, 1 sync/iter ----------------------
#define GBM 128
#define GBN 64
#define GBK 32
#define STAGES 3
#define AS_STRIDE 40
#define BS_STRIDE 72
#define KITERS 8        // 256 / GBK

__device__ __forceinline__ void cp16(unsigned dst, const void* src) {
    asm volatile("cp.async.cg.shared.global [%0], [%1], 16;\n" :: "r"(dst), "l"(src));
}
__device__ __forceinline__ void cp_commit() {
    asm volatile("cp.async.commit_group;\n");
}
template <int N>
__device__ __forceinline__ void cp_wait() {
    asm volatile("cp.async.wait_group %0;\n" :: "n"(N));
}
__device__ __forceinline__ void ldm_x4(unsigned& r0, unsigned& r1,
                                       unsigned& r2, unsigned& r3, unsigned addr) {
    asm volatile("ldmatrix.sync.aligned.m8n8.x4.shared.b16 {%0,%1,%2,%3}, [%4];"
                 : "=r"(r0), "=r"(r1), "=r"(r2), "=r"(r3) : "r"(addr));
}
__device__ __forceinline__ void ldm_x4_t(unsigned& r0, unsigned& r1,
                                         unsigned& r2, unsigned& r3, unsigned addr) {
    asm volatile("ldmatrix.sync.aligned.m8n8.x4.trans.shared.b16 {%0,%1,%2,%3}, [%4];"
                 : "=r"(r0), "=r"(r1), "=r"(r2), "=r"(r3) : "r"(addr));
}
__device__ __forceinline__ void mma16816(float& c0, float& c1, float& c2, float& c3,
                                         unsigned a0, unsigned a1, unsigned a2, unsigned a3,
                                         unsigned b0, unsigned b1) {
    asm volatile(
        "mma.sync.aligned.m16n8k16.row.col.f32.f16.f16.f32 "
        "{%0,%1,%2,%3}, {%4,%5,%6,%7}, {%8,%9}, {%0,%1,%2,%3};"
        : "+f"(c0), "+f"(c1), "+f"(c2), "+f"(c3)
        : "r"(a0), "r"(a1), "r"(a2), "r"(a3), "r"(b0), "r"(b1));
}

template <typename OutT>
__global__ __launch_bounds__(256, 2)
void hgemm_k256(const __half* __restrict__ A,
                const __half* __restrict__ B,
                const float* __restrict__ bias,
                OutT* __restrict__ C, int N) {
    __shared__ __half As[STAGES][GBM][AS_STRIDE];
    __shared__ __half Bs[STAGES][GBK][BS_STRIDE];

    const int tid  = threadIdx.x;
    const int lane = tid & 31;
    const int warp = tid >> 5;
    const int wm = warp >> 1;
    const int wn = warp & 1;
    const int row0 = blockIdx.x * GBM;
    const int col0 = blockIdx.y * GBN;

    // cp.async mapping
    // A: 512 x 16B chunks; chunk c: row=c>>2, col16=c&3
    const int a_r0 = tid >> 2;             // rows for chunk i=0 (0..63), i=1 adds 64
    const int a_c  = (tid & 3) << 3;       // half offset 0,8,16,24
    // B: 256 x 16B chunks; row=tid>>3, col16=tid&7
    const int b_r = tid >> 3;
    const int b_c = (tid & 7) << 3;

    const __half* Aptr = A + (size_t)row0 * 256;
    const __half* Bptr = B + col0;

    auto issue_stage = [&](int s, int k0) {
        unsigned da0 = (unsigned)__cvta_generic_to_shared(&As[s][a_r0][a_c]);
        unsigned da1 = (unsigned)__cvta_generic_to_shared(&As[s][a_r0 + 64][a_c]);
        unsigned db  = (unsigned)__cvta_generic_to_shared(&Bs[s][b_r][b_c]);
        cp16(da0, Aptr + (size_t)a_r0 * 256 + k0 + a_c);
        cp16(da1, Aptr + (size_t)(a_r0 + 64) * 256 + k0 + a_c);
        cp16(db,  Bptr + (size_t)(k0 + b_r) * N + b_c);
    };

    // prologue: stages 0,1
    issue_stage(0, 0);  cp_commit();
    issue_stage(1, GBK); cp_commit();

    float acc[2][4][4] = {};
    const int a_lrow = lane & 15;
    const int a_lcol = (lane >> 4) << 3;

    #pragma unroll 1
    for (int t = 0; t < KITERS; t++) {
        const int sb = t % STAGES;
        cp_wait<STAGES - 2>();
        __syncthreads();

        // issue stage t+STAGES-1 (overwrites buffer computed at iter t-1)
        if (t + STAGES - 1 < KITERS)
            issue_stage((t + STAGES - 1) % STAGES, (t + STAGES - 1) * GBK);
        cp_commit();

        #pragma unroll
        for (int ks = 0; ks < 2; ks++) {
            const int kk = ks * 16;
            unsigned af[2][4], bf[4][2];
            #pragma unroll
            for (int mt = 0; mt < 2; mt++) {
                unsigned addr = (unsigned)__cvta_generic_to_shared(
                    &As[sb][wm * 32 + mt * 16 + a_lrow][kk + a_lcol]);
                ldm_x4(af[mt][0], af[mt][1], af[mt][2], af[mt][3], addr);
            }
            #pragma unroll
            for (int nt = 0; nt < 2; nt++) {
                unsigned addr = (unsigned)__cvta_generic_to_shared(
                    &Bs[sb][kk + a_lrow][wn * 32 + nt * 16 + a_lcol]);
                unsigned r0, r1, r2, r3;
                ldm_x4_t(r0, r1, r2, r3, addr);
                bf[nt * 2 + 0][0] = r0; bf[nt * 2 + 0][1] = r1;
                bf[nt * 2 + 1][0] = r2; bf[nt * 2 + 1][1] = r3;
            }
            #pragma unroll
            for (int mt = 0; mt < 2; mt++)
                #pragma unroll
                for (int j = 0; j < 4; j++)
                    mma16816(acc[mt][j][0], acc[mt][j][1], acc[mt][j][2], acc[mt][j][3],
                             af[mt][0], af[mt][1], af[mt][2], af[mt][3],
                             bf[j][0], bf[j][1]);
        }
        __syncthreads();
    }

    const int g  = lane >> 2;
    const int tq = (lane & 3) << 1;
    #pragma unroll
    for (int mt = 0; mt < 2; mt++) {
        int r_lo = row0 + wm * 32 + mt * 16 + g;
        #pragma unroll
        for (int j = 0; j < 4; j++) {
            int c = col0 + wn * 32 + j * 8 + tq;
            float b0 = bias[c], b1 = bias[c + 1];
            C[(size_t)r_lo * N + c]           = (OutT)(acc[mt][j][0] + b0);
            C[(size_t)r_lo * N + c + 1]       = (OutT)(acc[mt][j][1] + b1);
            C[(size_t)(r_lo + 8) * N + c]     = (OutT)(acc[mt][j][2] + b0);
            C[(size_t)(r_lo + 8) * N + c + 1] = (OutT)(acc[mt][j][3] + b1);
        }
    }
}

// ---------------- fused softmax + deformable sampling (uint4 loads) ---------
// one block per query: 128 threads = 4 warps = 4 heads.
// lane: g = lane>>3 (point subgroup), j = lane&7 (8-dim chunk).
__global__ __launch_bounds__(128)
void sample_kernel(const float* __restrict__ refpts,
                   const float* __restrict__ oa,
                   const __half* __restrict__ value,
                   __half* __restrict__ out) {
    __shared__ float s_off[HLP2];
    __shared__ float s_attn[HLP];
    __shared__ float s_ref[8];

    const int nq  = blockIdx.x;
    const int tid = threadIdx.x;
    const float* row = oa + (size_t)nq * NOA;

    s_off[tid]       = row[tid];
    s_off[tid + 128] = row[tid + 128];
    {
        float v = row[HLP2 + tid];
        float m = v;
        #pragma unroll
        for (int o = 16; o > 0; o >>= 1) m = fmaxf(m, __shfl_xor_sync(0xffffffffu, m, o));
        float e = expf(v - m);
        float s = e;
        #pragma unroll
        for (int o = 16; o > 0; o >>= 1) s += __shfl_xor_sync(0xffffffffu, s, o);
        s_attn[tid] = e / s;
    }
    if (tid < 8) s_ref[tid] = refpts[(size_t)nq * 8 + tid];
    __syncthreads();

    const int h    = tid >> 5;
    const int lane = tid & 31;
    const int g    = lane >> 3;
    const int j    = lane & 7;
    const int lvlS[4] = {0, 4096, 5120, 5376};

    // uint4 view of value: 32 uint4 per position row
    const uint4* vrow = (const uint4*)value + (size_t)(nq / LQ) * LIN * 32 + h * 8 + j;
    float acc[8] = {};

    #pragma unroll
    for (int l = 0; l < 4; l++) {
        const int Wl = 64 >> l;
        const float gxb = s_ref[l * 2 + 0] * (float)Wl - 0.5f;
        const float gyb = s_ref[l * 2 + 1] * (float)Wl - 0.5f;
        const uint4* vl = vrow + (size_t)lvlS[l] * 32;

        #pragma unroll
        for (int p8 = 0; p8 < 2; p8++) {
            const int p  = p8 * 4 + g;
            const int pi = (h * LL + l) * PP + p;
            float gx = gxb + s_off[pi * 2 + 0];
            float gy = gyb + s_off[pi * 2 + 1];
            float a  = s_attn[pi];

            float x0f = floorf(gx), y0f = floorf(gy);
            int x0 = (int)x0f, y0 = (int)y0f;
            float wx1 = gx - x0f, wy1 = gy - y0f;
            float wx0 = 1.f - wx1, wy0 = 1.f - wy1;

            bool xin0 = (x0 >= 0) & (x0 < Wl);
            bool xin1 = (x0 + 1 >= 0) & (x0 + 1 < Wl);
            bool yin0 = (y0 >= 0) & (y0 < Wl);
            bool yin1 = (y0 + 1 >= 0) & (y0 + 1 < Wl);
            int xc0 = min(max(x0, 0), Wl - 1);
            int xc1 = min(max(x0 + 1, 0), Wl - 1);
            int yc0 = min(max(y0, 0), Wl - 1);
            int yc1 = min(max(y0 + 1, 0), Wl - 1);

            uint4 c00 = {0,0,0,0}, c01 = {0,0,0,0}, c10 = {0,0,0,0}, c11 = {0,0,0,0};
            if (yin0 && xin0) c00 = vl[(size_t)(yc0 * Wl + xc0) * 32];
            if (yin0 && xin1) c01 = vl[(size_t)(yc0 * Wl + xc1) * 32];
            if (yin1 && xin0) c10 = vl[(size_t)(yc1 * Wl + xc0) * 32];
            if (yin1 && xin1) c11 = vl[(size_t)(yc1 * Wl + xc1) * 32];

            float w00 = a * wy0 * wx0, w01 = a * wy0 * wx1;
            float w10 = a * wy1 * wx0, w11 = a * wy1 * wx1;

            const __half2* p00 = (const __half2*)&c00;
            const __half2* p01 = (const __half2*)&c01;
            const __half2* p10 = (const __half2*)&c10;
            const __half2* p11 = (const __half2*)&c11;
            #pragma unroll
            for (int k = 0; k < 4; k++) {
                float2 f00 = __half22float2(p00[k]);
                float2 f01 = __half22float2(p01[k]);
                float2 f10 = __half22float2(p10[k]);
                float2 f11 = __half22float2(p11[k]);
                acc[2*k]   += w00 * f00.x + w01 * f01.x + w10 * f10.x + w11 * f11.x;
                acc[2*k+1] += w00 * f00.y + w01 * f01.y + w10 * f10.y + w11 * f11.y;
            }
        }
    }

    // reduce over point subgroups (lanes differing in bits 3,4)
    #pragma unroll
    for (int i = 0; i < 8; i++) {
        acc[i] += __shfl_xor_sync(0xffffffffu, acc[i], 8);
        acc[i] += __shfl_xor_sync(0xffffffffu, acc[i], 16);
    }

    if (lane < 8) {
        __half2 h0 = __floats2half2_rn(acc[0], acc[1]);
        __half2 h1 = __floats2half2_rn(acc[2], acc[3]);
        __half2 h2 = __floats2half2_rn(acc[4], acc[5]);
        __half2 h3 = __floats2half2_rn(acc[6], acc[7]);
        uint4 o;
        o.x = *(unsigned*)&h0; o.y = *(unsigned*)&h1;
        o.z = *(unsigned*)&h2; o.w = *(unsigned*)&h3;
        ((uint4*)(out + (size_t)nq * CC + h * HD))[lane] = o;
    }
}

// ---------------- layernorm(src + attn_out) --------------------------------
__global__ __launch_bounds__(256)
void ln_kernel(const float* __restrict__ src,
               const float* __restrict__ attnout,
               const float* __restrict__ gamma,
               const float* __restrict__ beta,
               float* __restrict__ out) {
    int nq  = blockIdx.x;
    int tid = threadIdx.x;

    float x = src[(size_t)nq * CC + tid] + attnout[(size_t)nq * CC + tid];

    __shared__ float red[8];
    __shared__ float s_mean, s_rstd;

    float s = x;
    #pragma unroll
    for (int o = 16; o > 0; o >>= 1) s += __shfl_xor_sync(0xffffffffu, s, o);
    if ((tid & 31) == 0) red[tid >> 5] = s;
    __syncthreads();
    if (tid == 0) {
        float t = 0.f;
        #pragma unroll
        for (int i = 0; i < 8; i++) t += red[i];
        s_mean = t * (1.f / 256.f);
    }
    __syncthreads();
    float mean = s_mean;

    float dcen = x - mean;
    float v = dcen * dcen;
    #pragma unroll
    for (int o = 16; o > 0; o >>= 1) v += __shfl_xor_sync(0xffffffffu, v, o);
    if ((tid & 31) == 0) red[tid >> 5] = v;
    __syncthreads();
    if (tid == 0) {
        float t = 0.f;
        #pragma unroll
        for (int i = 0; i < 8; i++) t += red[i];
        s_rstd = rsqrtf(t * (1.f / 256.f) + 1e-5f);
    }
    __syncthreads();

    out[(size_t)nq * CC + tid] = dcen * s_rstd * gamma[tid] + beta[tid];
}

// ---------------- launcher --------------------------------------------------
extern "C" void kernel_launch(void* const* d_in, const int* in_sizes, int n_in,
                              void* d_out, int out_size) {
    const float* src_feat   = (const float*)d_in[0];
    const float* refpts     = (const float*)d_in[1];
    const float* key_feat   = (const float*)d_in[2];
    const float* query_pos  = (const float*)d_in[5];
    const float* W_value    = (const float*)d_in[6];
    const float* b_value    = (const float*)d_in[7];
    const float* W_off      = (const float*)d_in[8];
    const float* b_off      = (const float*)d_in[9];
    const float* W_attn     = (const float*)d_in[10];
    const float* b_attn     = (const float*)d_in[11];
    const float* W_out      = (const float*)d_in[12];
    const float* b_out      = (const float*)d_in[13];
    const float* ln_g       = (const float*)d_in[14];
    const float* ln_b       = (const float*)d_in[15];
    float* out = (float*)d_out;

    __half *qh, *keyh, *valueh, *Wvh, *Woah, *Woh, *sampledh;
    float *oa, *boa, *attnout;
    cudaGetSymbolAddress((void**)&qh,       g_q_h);
    cudaGetSymbolAddress((void**)&keyh,     g_key_h);
    cudaGetSymbolAddress((void**)&valueh,   g_value_h);
    cudaGetSymbolAddress((void**)&oa,       g_oa);
    cudaGetSymbolAddress((void**)&Wvh,      g_Wv_h);
    cudaGetSymbolAddress((void**)&Woah,     g_Woa_h);
    cudaGetSymbolAddress((void**)&Woh,      g_Wo_h);
    cudaGetSymbolAddress((void**)&boa,      g_boa);
    cudaGetSymbolAddress((void**)&sampledh, g_sampled_h);
    cudaGetSymbolAddress((void**)&attnout,  g_attnout);

    prep_inputs_kernel<<<(2 * N8 + 255) / 256, 256>>>(src_feat, query_pos, key_feat,
                                                      qh, keyh);
    prep_weights_kernel<<<(CC * NOA + 255) / 256, 256>>>(W_value, W_off, W_attn,
                                                         b_off, b_attn, W_out,
                                                         Wvh, Woah, Woh, boa);

    hgemm_k256<__half><<<dim3(NKV / GBM, CC / GBN), 256>>>(keyh, Wvh, b_value,
                                                           valueh, CC);
    hgemm_k256<float><<<dim3(NQ / GBM, NOA / GBN), 256>>>(qh, Woah, boa, oa, NOA);

    sample_kernel<<<NQ, 128>>>(refpts, oa, valueh, sampledh);

    hgemm_k256<float><<<dim3(NQ / GBM, CC / GBN), 256>>>(sampledh, Woh, b_out,
                                                         attnout, CC);
    ln_kernel<<<NQ, 256>>>(src_feat, attnout, ln_g, ln_b, out);
}

// round 5
// speedup vs baseline: 3.5008x; 1.0484x over previous
#include <cuda_runtime.h>
#include <cuda_fp16.h>
#include <math.h>

// ---------------- problem constants ----------------------------------------
#define NB   2
#define LQ   5440
#define CC   256
#define HH   4
#define LL   4
#define PP   8
#define HD   64
#define LIN  5440
#define NQ   (NB * LQ)   // 10880
#define NKV  (NB * LIN)  // 10880
#define HLP  128
#define HLP2 256
#define NOA  384

// ---------------- scratch ---------------------------------------------------
__device__ __half g_q_h[NQ * CC];
__device__ __half g_key_h[NKV * CC];
__device__ __half g_value_h[NKV * CC];
__device__ float  g_oa[NQ * NOA];
__device__ __half g_Wv_h[CC * CC];
__device__ __half g_Woa_h[CC * NOA];
__device__ __half g_Wo_h[CC * CC];
__device__ float  g_boa[NOA];
__device__ __half g_sampled_h[NQ * CC];
__device__ float  g_attnout[NQ * CC];

// ---------------- prep: q=src+pos (fp16), key->fp16, vectorized x8 ----------
#define N8 (NQ * CC / 8)
__global__ __launch_bounds__(256)
void prep_inputs_kernel(const float* __restrict__ src,
                        const float* __restrict__ pos,
                        const float* __restrict__ key,
                        __half* __restrict__ qh,
                        __half* __restrict__ keyh) {
    int i = blockIdx.x * blockDim.x + threadIdx.x;
    if (i < N8) {
        float4 s0 = ((const float4*)src)[i * 2];
        float4 s1 = ((const float4*)src)[i * 2 + 1];
        float4 p0 = ((const float4*)pos)[i * 2];
        float4 p1 = ((const float4*)pos)[i * 2 + 1];
        __half2 h0 = __floats2half2_rn(s0.x + p0.x, s0.y + p0.y);
        __half2 h1 = __floats2half2_rn(s0.z + p0.z, s0.w + p0.w);
        __half2 h2 = __floats2half2_rn(s1.x + p1.x, s1.y + p1.y);
        __half2 h3 = __floats2half2_rn(s1.z + p1.z, s1.w + p1.w);
        uint4 o;
        o.x = *(unsigned*)&h0; o.y = *(unsigned*)&h1;
        o.z = *(unsigned*)&h2; o.w = *(unsigned*)&h3;
        ((uint4*)qh)[i] = o;
    } else if (i < 2 * N8) {
        int j = i - N8;
        float4 k0 = ((const float4*)key)[j * 2];
        float4 k1 = ((const float4*)key)[j * 2 + 1];
        __half2 h0 = __floats2half2_rn(k0.x, k0.y);
        __half2 h1 = __floats2half2_rn(k0.z, k0.w);
        __half2 h2 = __floats2half2_rn(k1.x, k1.y);
        __half2 h3 = __floats2half2_rn(k1.z, k1.w);
        uint4 o;
        o.x = *(unsigned*)&h0; o.y = *(unsigned*)&h1;
        o.z = *(unsigned*)&h2; o.w = *(unsigned*)&h3;
        ((uint4*)keyh)[j] = o;
    }
}

// ---------------- prep: weights -> fp16 -------------------------------------
__global__ void prep_weights_kernel(const float* __restrict__ Wv,
                                    const float* __restrict__ Woff,
                                    const float* __restrict__ Wattn,
                                    const float* __restrict__ boff,
                                    const float* __restrict__ battn,
                                    const float* __restrict__ Wo,
                                    __half* __restrict__ Wvh,
                                    __half* __restrict__ Woah,
                                    __half* __restrict__ Woh,
                                    float* __restrict__ boa) {
    int i = blockIdx.x * blockDim.x + threadIdx.x;
    if (i < CC * CC) {
        Wvh[i] = __float2half(Wv[i]);
        Woh[i] = __float2half(Wo[i]);
    }
    if (i < CC * NOA) {
        int k = i / NOA, n = i % NOA;
        float w = (n < HLP2) ? Woff[k * HLP2 + n] : Wattn[k * HLP + (n - HLP2)];
        Woah[i] = __float2half(w);
    }
    if (i < NOA) boa[i] = (i < HLP2) ? boff[i] : battn[i - HLP2];
}

// ---------------- HGEMM: 64x64x32, 128 thr, 4-stage cp.async, 1 sync/iter ---
#define GBM 64
#define GBN 64
#define GBK 32
#define STAGES 4
#define AS_STRIDE 40
#define BS_STRIDE 72
#define KITERS 8        // 256 / GBK

__device__ __forceinline__ void cp16(unsigned dst, const void* src) {
    asm volatile("cp.async.cg.shared.global [%0], [%1], 16;\n" :: "r"(dst), "l"(src));
}
__device__ __forceinline__ void cp_commit() {
    asm volatile("cp.async.commit_group;\n");
}
template <int N>
__device__ __forceinline__ void cp_wait() {
    asm volatile("cp.async.wait_group %0;\n" :: "n"(N));
}
__device__ __forceinline__ void ldm_x4(unsigned& r0, unsigned& r1,
                                       unsigned& r2, unsigned& r3, unsigned addr) {
    asm volatile("ldmatrix.sync.aligned.m8n8.x4.shared.b16 {%0,%1,%2,%3}, [%4];"
                 : "=r"(r0), "=r"(r1), "=r"(r2), "=r"(r3) : "r"(addr));
}
__device__ __forceinline__ void ldm_x4_t(unsigned& r0, unsigned& r1,
                                         unsigned& r2, unsigned& r3, unsigned addr) {
    asm volatile("ldmatrix.sync.aligned.m8n8.x4.trans.shared.b16 {%0,%1,%2,%3}, [%4];"
                 : "=r"(r0), "=r"(r1), "=r"(r2), "=r"(r3) : "r"(addr));
}
__device__ __forceinline__ void mma16816(float& c0, float& c1, float& c2, float& c3,
                                         unsigned a0, unsigned a1, unsigned a2, unsigned a3,
                                         unsigned b0, unsigned b1) {
    asm volatile(
        "mma.sync.aligned.m16n8k16.row.col.f32.f16.f16.f32 "
        "{%0,%1,%2,%3}, {%4,%5,%6,%7}, {%8,%9}, {%0,%1,%2,%3};"
        : "+f"(c0), "+f"(c1), "+f"(c2), "+f"(c3)
        : "r"(a0), "r"(a1), "r"(a2), "r"(a3), "r"(b0), "r"(b1));
}

template <typename OutT>
__global__ __launch_bounds__(128, 5)
void hgemm_k256(const __half* __restrict__ A,
                const __half* __restrict__ B,
                const float* __restrict__ bias,
                OutT* __restrict__ C, int N) {
    __shared__ __half As[STAGES][GBM][AS_STRIDE];   // 4*64*40*2  = 20.0 KB
    __shared__ __half Bs[STAGES][GBK][BS_STRIDE];   // 4*32*72*2  = 18.0 KB

    const int tid  = threadIdx.x;
    const int lane = tid & 31;
    const int warp = tid >> 5;
    const int wm = warp >> 1;          // 0..1 -> m offset 32*wm
    const int wn = warp & 1;           // 0..1 -> n offset 32*wn
    const int row0 = blockIdx.x * GBM;
    const int col0 = blockIdx.y * GBN;

    // cp.async mapping (128 threads)
    // A tile: 64 rows x 32 halfs = 256 x 16B chunks; thread: rows a_r, a_r+32
    const int a_r = tid >> 2;              // 0..31
    const int a_c = (tid & 3) << 3;        // 0,8,16,24
    // B tile: 32 rows x 64 halfs = 256 chunks; thread: rows b_r, b_r+16
    const int b_r = tid >> 3;              // 0..15
    const int b_c = (tid & 7) << 3;        // 0..56

    const __half* Aptr = A + (size_t)row0 * 256;
    const __half* Bptr = B + col0;

    auto issue_stage = [&](int s, int k0) {
        cp16((unsigned)__cvta_generic_to_shared(&As[s][a_r][a_c]),
             Aptr + (size_t)a_r * 256 + k0 + a_c);
        cp16((unsigned)__cvta_generic_to_shared(&As[s][a_r + 32][a_c]),
             Aptr + (size_t)(a_r + 32) * 256 + k0 + a_c);
        cp16((unsigned)__cvta_generic_to_shared(&Bs[s][b_r][b_c]),
             Bptr + (size_t)(k0 + b_r) * N + b_c);
        cp16((unsigned)__cvta_generic_to_shared(&Bs[s][b_r + 16][b_c]),
             Bptr + (size_t)(k0 + b_r + 16) * N + b_c);
    };

    // prologue: stages 0..2
    issue_stage(0, 0);       cp_commit();
    issue_stage(1, GBK);     cp_commit();
    issue_stage(2, 2 * GBK); cp_commit();

    float acc[2][4][4] = {};
    const int a_lrow = lane & 15;
    const int a_lcol = (lane >> 4) << 3;

    #pragma unroll 1
    for (int t = 0; t < KITERS; t++) {
        const int sb = t & (STAGES - 1);
        cp_wait<STAGES - 2>();
        __syncthreads();               // also orders reuse of buffer (t-1)&3

        if (t + STAGES - 1 < KITERS)
            issue_stage((t + STAGES - 1) & (STAGES - 1), (t + STAGES - 1) * GBK);
        cp_commit();

        #pragma unroll
        for (int ks = 0; ks < 2; ks++) {
            const int kk = ks * 16;
            unsigned af[2][4], bf[4][2];
            #pragma unroll
            for (int mt = 0; mt < 2; mt++) {
                unsigned addr = (unsigned)__cvta_generic_to_shared(
                    &As[sb][wm * 32 + mt * 16 + a_lrow][kk + a_lcol]);
                ldm_x4(af[mt][0], af[mt][1], af[mt][2], af[mt][3], addr);
            }
            #pragma unroll
            for (int nt = 0; nt < 2; nt++) {
                unsigned addr = (unsigned)__cvta_generic_to_shared(
                    &Bs[sb][kk + a_lrow][wn * 32 + nt * 16 + a_lcol]);
                unsigned r0, r1, r2, r3;
                ldm_x4_t(r0, r1, r2, r3, addr);
                bf[nt * 2 + 0][0] = r0; bf[nt * 2 + 0][1] = r1;
                bf[nt * 2 + 1][0] = r2; bf[nt * 2 + 1][1] = r3;
            }
            #pragma unroll
            for (int mt = 0; mt < 2; mt++)
                #pragma unroll
                for (int j = 0; j < 4; j++)
                    mma16816(acc[mt][j][0], acc[mt][j][1], acc[mt][j][2], acc[mt][j][3],
                             af[mt][0], af[mt][1], af[mt][2], af[mt][3],
                             bf[j][0], bf[j][1]);
        }
        // no trailing sync: next-iter top barrier orders buffer reuse
    }

    const int g  = lane >> 2;
    const int tq = (lane & 3) << 1;
    #pragma unroll
    for (int mt = 0; mt < 2; mt++) {
        int r_lo = row0 + wm * 32 + mt * 16 + g;
        #pragma unroll
        for (int j = 0; j < 4; j++) {
            int c = col0 + wn * 32 + j * 8 + tq;
            float b0 = bias[c], b1 = bias[c + 1];
            C[(size_t)r_lo * N + c]           = (OutT)(acc[mt][j][0] + b0);
            C[(size_t)r_lo * N + c + 1]       = (OutT)(acc[mt][j][1] + b1);
            C[(size_t)(r_lo + 8) * N + c]     = (OutT)(acc[mt][j][2] + b0);
            C[(size_t)(r_lo + 8) * N + c + 1] = (OutT)(acc[mt][j][3] + b1);
        }
    }
}

// ---------------- fused softmax + deformable sampling (2 queries/block) -----
// 256 threads = 2 queries x (4 warps = 4 heads); lane: g=lane>>3 point group,
// j=lane&7 dim chunk (uint4 = 8 halfs).
__global__ __launch_bounds__(256)
void sample_kernel(const float* __restrict__ refpts,
                   const float* __restrict__ oa,
                   const __half* __restrict__ value,
                   __half* __restrict__ out) {
    __shared__ float s_off[2][HLP2];
    __shared__ float s_attn[2][HLP];
    __shared__ float s_ref[2][8];

    const int tid  = threadIdx.x;
    const int sub  = tid >> 7;               // query within pair
    const int t128 = tid & 127;
    const int nq   = blockIdx.x * 2 + sub;
    const float* row = oa + (size_t)nq * NOA;

    s_off[sub][t128]       = row[t128];
    s_off[sub][t128 + 128] = row[t128 + 128];
    {
        float v = row[HLP2 + t128];
        float m = v;
        #pragma unroll
        for (int o = 16; o > 0; o >>= 1) m = fmaxf(m, __shfl_xor_sync(0xffffffffu, m, o));
        float e = expf(v - m);
        float s = e;
        #pragma unroll
        for (int o = 16; o > 0; o >>= 1) s += __shfl_xor_sync(0xffffffffu, s, o);
        s_attn[sub][t128] = e / s;
    }
    if (t128 < 8) s_ref[sub][t128] = refpts[(size_t)nq * 8 + t128];
    __syncthreads();

    const int h    = t128 >> 5;
    const int lane = tid & 31;
    const int g    = lane >> 3;
    const int j    = lane & 7;
    const int lvlS[4] = {0, 4096, 5120, 5376};

    const uint4* vrow = (const uint4*)value + (size_t)(nq / LQ) * LIN * 32 + h * 8 + j;
    float acc[8] = {};

    #pragma unroll
    for (int l = 0; l < 4; l++) {
        const int Wl = 64 >> l;
        const float gxb = s_ref[sub][l * 2 + 0] * (float)Wl - 0.5f;
        const float gyb = s_ref[sub][l * 2 + 1] * (float)Wl - 0.5f;
        const uint4* vl = vrow + (size_t)lvlS[l] * 32;

        #pragma unroll
        for (int p8 = 0; p8 < 2; p8++) {
            const int p  = p8 * 4 + g;
            const int pi = (h * LL + l) * PP + p;
            float gx = gxb + s_off[sub][pi * 2 + 0];
            float gy = gyb + s_off[sub][pi * 2 + 1];
            float a  = s_attn[sub][pi];

            float x0f = floorf(gx), y0f = floorf(gy);
            int x0 = (int)x0f, y0 = (int)y0f;
            float wx1 = gx - x0f, wy1 = gy - y0f;
            float wx0 = 1.f - wx1, wy0 = 1.f - wy1;

            bool xin0 = (x0 >= 0) & (x0 < Wl);
            bool xin1 = (x0 + 1 >= 0) & (x0 + 1 < Wl);
            bool yin0 = (y0 >= 0) & (y0 < Wl);
            bool yin1 = (y0 + 1 >= 0) & (y0 + 1 < Wl);
            int xc0 = min(max(x0, 0), Wl - 1);
            int xc1 = min(max(x0 + 1, 0), Wl - 1);
            int yc0 = min(max(y0, 0), Wl - 1);
            int yc1 = min(max(y0 + 1, 0), Wl - 1);

            uint4 c00 = {0,0,0,0}, c01 = {0,0,0,0}, c10 = {0,0,0,0}, c11 = {0,0,0,0};
            if (yin0 && xin0) c00 = vl[(size_t)(yc0 * Wl + xc0) * 32];
            if (yin0 && xin1) c01 = vl[(size_t)(yc0 * Wl + xc1) * 32];
            if (yin1 && xin0) c10 = vl[(size_t)(yc1 * Wl + xc0) * 32];
            if (yin1 && xin1) c11 = vl[(size_t)(yc1 * Wl + xc1) * 32];

            float w00 = a * wy0 * wx0, w01 = a * wy0 * wx1;
            float w10 = a * wy1 * wx0, w11 = a * wy1 * wx1;

            const __half2* p00 = (const __half2*)&c00;
            const __half2* p01 = (const __half2*)&c01;
            const __half2* p10 = (const __half2*)&c10;
            const __half2* p11 = (const __half2*)&c11;
            #pragma unroll
            for (int k = 0; k < 4; k++) {
                float2 f00 = __half22float2(p00[k]);
                float2 f01 = __half22float2(p01[k]);
                float2 f10 = __half22float2(p10[k]);
                float2 f11 = __half22float2(p11[k]);
                acc[2*k]   += w00 * f00.x + w01 * f01.x + w10 * f10.x + w11 * f11.x;
                acc[2*k+1] += w00 * f00.y + w01 * f01.y + w10 * f10.y + w11 * f11.y;
            }
        }
    }

    #pragma unroll
    for (int i = 0; i < 8; i++) {
        acc[i] += __shfl_xor_sync(0xffffffffu, acc[i], 8);
        acc[i] += __shfl_xor_sync(0xffffffffu, acc[i], 16);
    }

    if (lane < 8) {
        __half2 h0 = __floats2half2_rn(acc[0], acc[1]);
        __half2 h1 = __floats2half2_rn(acc[2], acc[3]);
        __half2 h2 = __floats2half2_rn(acc[4], acc[5]);
        __half2 h3 = __floats2half2_rn(acc[6], acc[7]);
        uint4 o;
        o.x = *(unsigned*)&h0; o.y = *(unsigned*)&h1;
        o.z = *(unsigned*)&h2; o.w = *(unsigned*)&h3;
        ((uint4*)(out + (size_t)nq * CC + h * HD))[lane] = o;
    }
}

// ---------------- layernorm(src + attn_out) --------------------------------
__global__ __launch_bounds__(256)
void ln_kernel(const float* __restrict__ src,
               const float* __restrict__ attnout,
               const float* __restrict__ gamma,
               const float* __restrict__ beta,
               float* __restrict__ out) {
    int nq  = blockIdx.x;
    int tid = threadIdx.x;

    float x = src[(size_t)nq * CC + tid] + attnout[(size_t)nq * CC + tid];

    __shared__ float red[8];
    __shared__ float s_mean, s_rstd;

    float s = x;
    #pragma unroll
    for (int o = 16; o > 0; o >>= 1) s += __shfl_xor_sync(0xffffffffu, s, o);
    if ((tid & 31) == 0) red[tid >> 5] = s;
    __syncthreads();
    if (tid == 0) {
        float t = 0.f;
        #pragma unroll
        for (int i = 0; i < 8; i++) t += red[i];
        s_mean = t * (1.f / 256.f);
    }
    __syncthreads();
    float mean = s_mean;

    float dcen = x - mean;
    float v = dcen * dcen;
    #pragma unroll
    for (int o = 16; o > 0; o >>= 1) v += __shfl_xor_sync(0xffffffffu, v, o);
    if ((tid & 31) == 0) red[tid >> 5] = v;
    __syncthreads();
    if (tid == 0) {
        float t = 0.f;
        #pragma unroll
        for (int i = 0; i < 8; i++) t += red[i];
        s_rstd = rsqrtf(t * (1.f / 256.f) + 1e-5f);
    }
    __syncthreads();

    out[(size_t)nq * CC + tid] = dcen * s_rstd * gamma[tid] + beta[tid];
}

// ---------------- launcher --------------------------------------------------
extern "C" void kernel_launch(void* const* d_in, const int* in_sizes, int n_in,
                              void* d_out, int out_size) {
    const float* src_feat   = (const float*)d_in[0];
    const float* refpts     = (const float*)d_in[1];
    const float* key_feat   = (const float*)d_in[2];
    const float* query_pos  = (const float*)d_in[5];
    const float* W_value    = (const float*)d_in[6];
    const float* b_value    = (const float*)d_in[7];
    const float* W_off      = (const float*)d_in[8];
    const float* b_off      = (const float*)d_in[9];
    const float* W_attn     = (const float*)d_in[10];
    const float* b_attn     = (const float*)d_in[11];
    const float* W_out      = (const float*)d_in[12];
    const float* b_out      = (const float*)d_in[13];
    const float* ln_g       = (const float*)d_in[14];
    const float* ln_b       = (const float*)d_in[15];
    float* out = (float*)d_out;

    __half *qh, *keyh, *valueh, *Wvh, *Woah, *Woh, *sampledh;
    float *oa, *boa, *attnout;
    cudaGetSymbolAddress((void**)&qh,       g_q_h);
    cudaGetSymbolAddress((void**)&keyh,     g_key_h);
    cudaGetSymbolAddress((void**)&valueh,   g_value_h);
    cudaGetSymbolAddress((void**)&oa,       g_oa);
    cudaGetSymbolAddress((void**)&Wvh,      g_Wv_h);
    cudaGetSymbolAddress((void**)&Woah,     g_Woa_h);
    cudaGetSymbolAddress((void**)&Woh,      g_Wo_h);
    cudaGetSymbolAddress((void**)&boa,      g_boa);
    cudaGetSymbolAddress((void**)&sampledh, g_sampled_h);
    cudaGetSymbolAddress((void**)&attnout,  g_attnout);

    prep_inputs_kernel<<<(2 * N8 + 255) / 256, 256>>>(src_feat, query_pos, key_feat,
                                                      qh, keyh);
    prep_weights_kernel<<<(CC * NOA + 255) / 256, 256>>>(W_value, W_off, W_attn,
                                                         b_off, b_attn, W_out,
                                                         Wvh, Woah, Woh, boa);

    hgemm_k256<__half><<<dim3(NKV / GBM, CC / GBN), 128>>>(keyh, Wvh, b_value,
                                                           valueh, CC);
    hgemm_k256<float><<<dim3(NQ / GBM, NOA / GBN), 128>>>(qh, Woah, boa, oa, NOA);

    sample_kernel<<<NQ / 2, 256>>>(refpts, oa, valueh, sampledh);

    hgemm_k256<float><<<dim3(NQ / GBM, CC / GBN), 128>>>(sampledh, Woh, b_out,
                                                         attnout, CC);
    ln_kernel<<<NQ, 256>>>(src_feat, attnout, ln_g, ln_b, out);
}